// round 2
// baseline (speedup 1.0000x reference)
#include <cuda_runtime.h>
#include <math.h>

// Problem constants
#define BN     256   // batch
#define HN     128   // hidden
#define CN     32    // input channels
#define OUTN   32
#define NSTEP  64
#define NSTAGE 256   // 64 steps * 4 RK stages
#define GRID   128   // persistent CTAs (1 per SM guaranteed by smem usage; 128 <= 148)

// ---------------- device global scratch (allocation-free) ----------------
__device__ float g_z0[BN * HN];        // z0 of current step, per batch row
__device__ float g_k[4][BN * HN];      // k1..k4 of current step
__device__ float g_Bv[BN * HN];        // h2 = softplus(softplus(y W1)W2) for current stage
__device__ float g_dX[BN * CN];        // dX/dt at current stage time
__device__ unsigned long long g_bar;   // grid barrier counter (memset to 0 each launch)

struct SmemLayout {
    float W3s[128][256];   // 128 KB : this CTA's 8-h slice of W3  [i][hl*32+c]
    float W1s[128][128];   // 64 KB  : W1 cached (phase 1)
    float Bvs[32][129];    // padded : staged h2 rows for this CTA's 32-b tile
    float dXs[32][33];     // staged dX rows
    float ys[2][128];      // phase-1 y staging (2 batch rows per CTA)
    float As[2][128];      // phase-1 intermediate
};

__device__ __forceinline__ float softplus_f(float x) {
    // stable: max(x,0) + log1p(exp(-|x|))  (== jax.nn.softplus)
    return fmaxf(x, 0.0f) + log1pf(expf(-fabsf(x)));
}

__device__ __forceinline__ void grid_barrier(unsigned long long tgt) {
    __syncthreads();
    if (threadIdx.x == 0) {
        __threadfence();
        atomicAdd(&g_bar, 1ULL);
        while (*(volatile unsigned long long*)&g_bar < tgt) { }
    }
    __syncthreads();
}

__global__ __launch_bounds__(256, 1) void cde_kernel(
    const float* __restrict__ coeffs, const float* __restrict__ x_last,
    const float* __restrict__ Wi,     const float* __restrict__ bi,
    const float* __restrict__ W1,     const float* __restrict__ b1,
    const float* __restrict__ W2,     const float* __restrict__ b2,
    const float* __restrict__ W3,     const float* __restrict__ b3,
    const float* __restrict__ Wr,     const float* __restrict__ br,
    float* __restrict__ out)
{
    extern __shared__ char smraw[];
    SmemLayout& sm = *reinterpret_cast<SmemLayout*>(smraw);

    const int tid = threadIdx.x;
    const int ci  = blockIdx.x;
    const int hg  = ci & 15;      // h-group: this CTA owns h in [hg*8, hg*8+8)
    const int bg  = ci >> 4;      // b-group for phase 2: b in [bg*32, bg*32+32)
    const int bB  = bg * 32;

    // ---- one-time smem loads ----
    for (int t = tid; t < 128 * 256; t += 256) {
        int i = t >> 8, cc = t & 255;
        sm.W3s[i][cc] = W3[i * 4096 + hg * 256 + cc];
    }
    for (int t = tid; t < 128 * 128; t += 256)
        sm.W1s[t >> 7][t & 127] = W1[t];

    // phase-2 thread mapping: warp = local h; lane = (bgr,cg)
    const int wl   = tid >> 5;        // 0..7  -> local h
    const int lane = tid & 31;
    const int cg   = lane & 7;        // 8 c-groups of 4
    const int bgr  = lane >> 3;       // 4 b-groups of 8
    const int c0   = cg * 4;
    const int b0l  = bgr * 8;
    const int h    = hg * 8 + wl;     // global h for this warp

    float b3v[4];
    #pragma unroll
    for (int u = 0; u < 4; u++) b3v[u] = b3[h * 32 + c0 + u];

    __syncthreads();

    const int bP1 = ci * 2;           // phase-1: this CTA owns batch rows bP1, bP1+1
    const int bb  = tid >> 7;         // 0/1
    const int j   = tid & 127;
    const int bme = bP1 + bb;

    for (int s = 0; s < NSTAGE; s++) {
        const int s4 = s & 3;
        const int n  = s >> 2;

        // ================= phase 1 : y, dX, h1, h2 (b-split, 2 rows/CTA) ===========
        {
            float y;
            if (s == 0) {
                float acc = bi[j];
                const float* cb = coeffs + bme * 8192;     // piece 0, 'a' block
                #pragma unroll
                for (int c = 0; c < CN; c++) acc = fmaf(cb[c], Wi[c * 128 + j], acc);
                g_z0[bme * 128 + j] = acc;
                y = acc;
            } else {
                float z0 = g_z0[bme * 128 + j];
                if (s4 == 0) {  // fold previous step's k1..k4, advance z0
                    float k1 = __ldcg(&g_k[0][bme * 128 + j]);
                    float k2 = __ldcg(&g_k[1][bme * 128 + j]);
                    float k3 = __ldcg(&g_k[2][bme * 128 + j]);
                    float k4 = __ldcg(&g_k[3][bme * 128 + j]);
                    z0 += (k1 + 3.0f * (k2 + k3) + k4) * 0.125f;
                    g_z0[bme * 128 + j] = z0;
                    y = z0;
                } else if (s4 == 1) {
                    y = z0 + __ldcg(&g_k[0][bme * 128 + j]) * (1.0f / 3.0f);
                } else if (s4 == 2) {
                    y = z0 + __ldcg(&g_k[1][bme * 128 + j])
                           - __ldcg(&g_k[0][bme * 128 + j]) * (1.0f / 3.0f);
                } else {
                    y = z0 + __ldcg(&g_k[0][bme * 128 + j])
                           - __ldcg(&g_k[1][bme * 128 + j])
                           + __ldcg(&g_k[2][bme * 128 + j]);
                }
            }
            sm.ys[bb][j] = y;

            if (j < CN) {  // dX/dt at stage time (match fp32 arithmetic of reference)
                float t;
                if      (s4 == 0) t = (float)n;
                else if (s4 == 1) t = (float)n + (1.0f / 3.0f);
                else if (s4 == 2) t = (float)n + (2.0f / 3.0f);
                else              t = (float)(n + 1);
                int   pid  = (int)floorf(t); if (pid > 63) pid = 63;
                float frac = t - (float)pid;
                const float* cb = coeffs + bme * 8192 + pid * 128;
                float dv = fmaf(fmaf(cb[96 + j], frac, cb[64 + j]), frac, cb[32 + j]);
                __stcg(&g_dX[bme * 32 + j], dv);
            }
            __syncthreads();

            float acc = b1[j];
            #pragma unroll 4
            for (int i = 0; i < 128; i++) acc = fmaf(sm.ys[bb][i], sm.W1s[i][j], acc);
            sm.As[bb][j] = softplus_f(acc);
            __syncthreads();

            acc = b2[j];
            #pragma unroll 4
            for (int i = 0; i < 128; i++) acc = fmaf(sm.As[bb][i], __ldg(&W2[i * 128 + j]), acc);
            __stcg(&g_Bv[bme * 128 + j], softplus_f(acc));
        }

        grid_barrier((unsigned long long)(2 * s + 1) * GRID);

        // ================= phase 2 : k = tanh(h2 @ W3 + b3) . dX  (32b x 8h tile) ===
        {
            for (int t = tid; t < 32 * 128; t += 256) {
                int r = t >> 7, q = t & 127;
                sm.Bvs[r][q] = __ldcg(&g_Bv[(bB + r) * 128 + q]);
            }
            for (int t = tid; t < 32 * 32; t += 256) {
                int r = t >> 5, q = t & 31;
                sm.dXs[r][q] = __ldcg(&g_dX[(bB + r) * 32 + q]);
            }
            __syncthreads();

            float acc[8][4];
            #pragma unroll
            for (int jb = 0; jb < 8; jb++)
                #pragma unroll
                for (int u = 0; u < 4; u++) acc[jb][u] = 0.0f;

            #pragma unroll 4
            for (int i = 0; i < 128; i++) {
                float4 w4 = *reinterpret_cast<const float4*>(&sm.W3s[i][wl * 32 + c0]);
                #pragma unroll
                for (int jb = 0; jb < 8; jb++) {
                    float rb = sm.Bvs[b0l + jb][i];
                    acc[jb][0] = fmaf(rb, w4.x, acc[jb][0]);
                    acc[jb][1] = fmaf(rb, w4.y, acc[jb][1]);
                    acc[jb][2] = fmaf(rb, w4.z, acc[jb][2]);
                    acc[jb][3] = fmaf(rb, w4.w, acc[jb][3]);
                }
            }

            float pj[8];
            #pragma unroll
            for (int jb = 0; jb < 8; jb++) {
                float sacc = 0.0f;
                #pragma unroll
                for (int u = 0; u < 4; u++)
                    sacc = fmaf(tanhf(acc[jb][u] + b3v[u]), sm.dXs[b0l + jb][c0 + u], sacc);
                pj[jb] = sacc;
            }
            #pragma unroll
            for (int m = 1; m < 8; m <<= 1)
                #pragma unroll
                for (int jb = 0; jb < 8; jb++)
                    pj[jb] += __shfl_xor_sync(0xffffffffu, pj[jb], m);

            if (cg == 0) {
                #pragma unroll
                for (int jb = 0; jb < 8; jb++)
                    __stcg(&g_k[s4][(bB + b0l + jb) * 128 + h], pj[jb]);
            }
        }

        grid_barrier((unsigned long long)(2 * s + 2) * GRID);
    }

    // ================= epilogue: fold last step, readout =================
    {
        float z0 = g_z0[bme * 128 + j];
        float k1 = __ldcg(&g_k[0][bme * 128 + j]);
        float k2 = __ldcg(&g_k[1][bme * 128 + j]);
        float k3 = __ldcg(&g_k[2][bme * 128 + j]);
        float k4 = __ldcg(&g_k[3][bme * 128 + j]);
        sm.ys[bb][j] = z0 + (k1 + 3.0f * (k2 + k3) + k4) * 0.125f;
        __syncthreads();
        if (j < OUTN) {
            float acc = br[j] + x_last[bme * OUTN + j];
            #pragma unroll 4
            for (int hh = 0; hh < 128; hh++)
                acc = fmaf(sm.ys[bb][hh], Wr[hh * OUTN + j], acc);
            out[bme * OUTN + j] = acc;
        }
    }
}

extern "C" void kernel_launch(void* const* d_in, const int* in_sizes, int n_in,
                              void* d_out, int out_size) {
    const float* coeffs = (const float*)d_in[0];
    const float* x_last = (const float*)d_in[1];
    const float* Wi     = (const float*)d_in[2];
    const float* bi     = (const float*)d_in[3];
    const float* W1     = (const float*)d_in[4];
    const float* b1     = (const float*)d_in[5];
    const float* W2     = (const float*)d_in[6];
    const float* b2     = (const float*)d_in[7];
    const float* W3     = (const float*)d_in[8];
    const float* b3     = (const float*)d_in[9];
    const float* Wr     = (const float*)d_in[10];
    const float* br     = (const float*)d_in[11];
    float* out = (float*)d_out;

    static const size_t SMEM = sizeof(SmemLayout);
    cudaFuncSetAttribute(cde_kernel, cudaFuncAttributeMaxDynamicSharedMemorySize, (int)SMEM);

    // reset grid-barrier counter (graph-capturable async memset)
    void* baraddr = nullptr;
    cudaGetSymbolAddress(&baraddr, g_bar);
    cudaMemsetAsync(baraddr, 0, sizeof(unsigned long long));

    cde_kernel<<<GRID, 256, SMEM>>>(coeffs, x_last, Wi, bi, W1, b1, W2, b2,
                                    W3, b3, Wr, br, out);
}

// round 3
// speedup vs baseline: 1.3949x; 1.3949x over previous
#include <cuda_runtime.h>
#include <math.h>

// Problem constants
#define BN     256
#define HN     128
#define CN     32
#define OUTN   32
#define NSTAGE 256   // 64 steps * 4 RK stages
#define GRID   128
#define NTHR   512

// ---------------- device global scratch (allocation-free) ----------------
__device__ float g_k[4][BN * HN];      // k1..k4 of current step
__device__ float g_Bv[BN * HN];        // h2 for current stage
__device__ float g_dX[BN * CN];        // dX/dt at current stage time
__device__ unsigned long long g_bar;   // grid barrier counter

struct SmemLayout {
    float W3s[128][256];     // 128 KB : this CTA's 8-h slice of W3 [i][wl*32+c]
    float W1s[128][128];     // 64 KB
    float BvT[128][36];      // transposed h2 tile [i][b], padded for LDS128
    float dXs[32][36];
    float ys[2][128];
    float As[2][128];
    float P[2][2][128];      // phase-1 partial sums [half][bb][j]
    float z0s[2][128];
    float b1s[128];
    float b2s[128];
};

__device__ __forceinline__ float softplus_f(float x) {
    return fmaxf(x, 0.0f) + log1pf(__expf(-fabsf(x)));
}
__device__ __forceinline__ float tanh_fast(float x) {
    float e = __expf(2.0f * x);
    return 1.0f - __fdividef(2.0f, e + 1.0f);
}
__device__ __forceinline__ unsigned long long pk2(float lo, float hi) {
    unsigned long long r;
    asm("mov.b64 %0, {%1,%2};" : "=l"(r) : "f"(lo), "f"(hi));
    return r;
}
__device__ __forceinline__ void unpk2(unsigned long long v, float& lo, float& hi) {
    asm("mov.b64 {%0,%1}, %2;" : "=f"(lo), "=f"(hi) : "l"(v));
}
__device__ __forceinline__ void ffma2(unsigned long long& d, unsigned long long a,
                                      unsigned long long b) {
    asm("fma.rn.f32x2 %0, %1, %2, %0;" : "+l"(d) : "l"(a), "l"(b));
}

__device__ __forceinline__ void grid_barrier(unsigned long long tgt) {
    __syncthreads();
    if (threadIdx.x == 0) {
        __threadfence();
        atomicAdd(&g_bar, 1ULL);
        while (*(volatile unsigned long long*)&g_bar < tgt) { }
    }
    __syncthreads();
}

__global__ __launch_bounds__(NTHR, 1) void cde_kernel(
    const float* __restrict__ coeffs, const float* __restrict__ x_last,
    const float* __restrict__ Wi,     const float* __restrict__ bi,
    const float* __restrict__ W1,     const float* __restrict__ b1,
    const float* __restrict__ W2,     const float* __restrict__ b2,
    const float* __restrict__ W3,     const float* __restrict__ b3,
    const float* __restrict__ Wr,     const float* __restrict__ br,
    float* __restrict__ out)
{
    extern __shared__ char smraw[];
    SmemLayout& sm = *reinterpret_cast<SmemLayout*>(smraw);

    const int tid = threadIdx.x;
    const int ci  = blockIdx.x;
    const int hg  = ci & 15;          // h-group: h in [hg*8, hg*8+8)
    const int bB  = (ci >> 4) * 32;   // phase-2 b-tile base

    // ---- one-time smem loads ----
    for (int t = tid; t < 128 * 256; t += NTHR) {
        int i = t >> 8, cc = t & 255;
        sm.W3s[i][cc] = W3[i * 4096 + hg * 256 + cc];
    }
    for (int t = tid; t < 128 * 128; t += NTHR)
        sm.W1s[t >> 7][t & 127] = W1[t];
    if (tid < 128) { sm.b1s[tid] = b1[tid]; sm.b2s[tid] = b2[tid]; }

    // ---- phase-2 mapping ----
    const int wid  = tid >> 5;
    const int lane = tid & 31;
    const int wl   = wid & 7;         // local h
    const int sub  = wid >> 3;        // b-half (0/1)
    const int cg   = lane & 7;        // c-group of 4
    const int bgr  = lane >> 3;       // b-group of 4
    const int c0   = cg * 4;
    const int b0l  = sub * 16 + bgr * 4;   // 4 b-rows per thread
    const int h    = hg * 8 + wl;

    float b3v[4];
    #pragma unroll
    for (int u = 0; u < 4; u++) b3v[u] = b3[h * 32 + c0 + u];

    // ---- phase-1 mapping ----
    const int half = tid >> 8;        // i-half (0/1)
    const int rem  = tid & 255;
    const int bb   = rem >> 7;        // batch row within CTA (0/1)
    const int j    = rem & 127;
    const int bme  = ci * 2 + bb;

    __syncthreads();

    for (int s = 0; s < NSTAGE; s++) {
        const int s4 = s & 3;
        const int n  = s >> 2;

        // ============ phase 1 : y, dX, h1, h2  (2 batch rows / CTA) ============
        if (half == 0) {
            float y;
            if (s == 0) {
                float acc = bi[j];
                const float* cb = coeffs + bme * 8192;
                #pragma unroll
                for (int c = 0; c < CN; c++) acc = fmaf(cb[c], Wi[c * 128 + j], acc);
                sm.z0s[bb][j] = acc;
                y = acc;
            } else {
                float z0 = sm.z0s[bb][j];
                if (s4 == 0) {
                    float k1 = __ldcg(&g_k[0][bme * 128 + j]);
                    float k2 = __ldcg(&g_k[1][bme * 128 + j]);
                    float k3 = __ldcg(&g_k[2][bme * 128 + j]);
                    float k4 = __ldcg(&g_k[3][bme * 128 + j]);
                    z0 += (k1 + 3.0f * (k2 + k3) + k4) * 0.125f;
                    sm.z0s[bb][j] = z0;
                    y = z0;
                } else if (s4 == 1) {
                    y = z0 + __ldcg(&g_k[0][bme * 128 + j]) * (1.0f / 3.0f);
                } else if (s4 == 2) {
                    y = z0 + __ldcg(&g_k[1][bme * 128 + j])
                           - __ldcg(&g_k[0][bme * 128 + j]) * (1.0f / 3.0f);
                } else {
                    y = z0 + __ldcg(&g_k[0][bme * 128 + j])
                           - __ldcg(&g_k[1][bme * 128 + j])
                           + __ldcg(&g_k[2][bme * 128 + j]);
                }
            }
            sm.ys[bb][j] = y;

            if (j < CN) {
                float t;
                if      (s4 == 0) t = (float)n;
                else if (s4 == 1) t = (float)n + (1.0f / 3.0f);
                else if (s4 == 2) t = (float)n + (2.0f / 3.0f);
                else              t = (float)(n + 1);
                int   pid  = (int)floorf(t); if (pid > 63) pid = 63;
                float frac = t - (float)pid;
                const float* cb = coeffs + bme * 8192 + pid * 128;
                float dv = fmaf(fmaf(cb[96 + j], frac, cb[64 + j]), frac, cb[32 + j]);
                __stcg(&g_dX[bme * 32 + j], dv);
            }
        }
        __syncthreads();

        {   // matvec1 (i-split over halves)
            const int i0 = half * 64;
            float acc = 0.0f;
            #pragma unroll 8
            for (int i = 0; i < 64; i++)
                acc = fmaf(sm.ys[bb][i0 + i], sm.W1s[i0 + i][j], acc);
            sm.P[half][bb][j] = acc;
        }
        __syncthreads();
        if (half == 0)
            sm.As[bb][j] = softplus_f(sm.P[0][bb][j] + sm.P[1][bb][j] + sm.b1s[j]);
        __syncthreads();
        {   // matvec2
            const int i0 = half * 64;
            float acc = 0.0f;
            #pragma unroll 8
            for (int i = 0; i < 64; i++)
                acc = fmaf(sm.As[bb][i0 + i], __ldg(&W2[(i0 + i) * 128 + j]), acc);
            sm.P[half][bb][j] = acc;
        }
        __syncthreads();
        if (half == 0)
            __stcg(&g_Bv[bme * 128 + j],
                   softplus_f(sm.P[0][bb][j] + sm.P[1][bb][j] + sm.b2s[j]));

        grid_barrier((unsigned long long)(2 * s + 1) * GRID);

        // ============ phase 2 : k = tanh(h2 @ W3 + b3) . dX  (32b x 8h) ============
        {
            for (int t = tid; t < 32 * 128; t += NTHR) {
                int r = t >> 7, q = t & 127;
                sm.BvT[q][r] = __ldcg(&g_Bv[(bB + r) * 128 + q]);
            }
            for (int t = tid; t < 32 * 32; t += NTHR) {
                int r = t >> 5, q = t & 31;
                sm.dXs[r][q] = __ldcg(&g_dX[(bB + r) * 32 + q]);
            }
            __syncthreads();

            unsigned long long acc[2][4];
            #pragma unroll
            for (int p = 0; p < 2; p++)
                #pragma unroll
                for (int u = 0; u < 4; u++) acc[p][u] = 0ULL;

            #pragma unroll 4
            for (int i = 0; i < 128; i++) {
                float4 w4 = *reinterpret_cast<const float4*>(&sm.W3s[i][wl * 32 + c0]);
                ulonglong2 bv = *reinterpret_cast<const ulonglong2*>(&sm.BvT[i][b0l]);
                unsigned long long w0 = pk2(w4.x, w4.x);
                unsigned long long w1d = pk2(w4.y, w4.y);
                unsigned long long w2d = pk2(w4.z, w4.z);
                unsigned long long w3d = pk2(w4.w, w4.w);
                ffma2(acc[0][0], bv.x, w0);
                ffma2(acc[0][1], bv.x, w1d);
                ffma2(acc[0][2], bv.x, w2d);
                ffma2(acc[0][3], bv.x, w3d);
                ffma2(acc[1][0], bv.y, w0);
                ffma2(acc[1][1], bv.y, w1d);
                ffma2(acc[1][2], bv.y, w2d);
                ffma2(acc[1][3], bv.y, w3d);
            }

            float pj[4] = {0.0f, 0.0f, 0.0f, 0.0f};
            #pragma unroll
            for (int p = 0; p < 2; p++) {
                #pragma unroll
                for (int u = 0; u < 4; u++) {
                    float lo, hi;
                    unpk2(acc[p][u], lo, hi);
                    pj[2 * p]     = fmaf(tanh_fast(lo + b3v[u]),
                                         sm.dXs[b0l + 2 * p][c0 + u], pj[2 * p]);
                    pj[2 * p + 1] = fmaf(tanh_fast(hi + b3v[u]),
                                         sm.dXs[b0l + 2 * p + 1][c0 + u], pj[2 * p + 1]);
                }
            }
            #pragma unroll
            for (int m = 1; m < 8; m <<= 1)
                #pragma unroll
                for (int r = 0; r < 4; r++)
                    pj[r] += __shfl_xor_sync(0xffffffffu, pj[r], m);

            if (cg == 0) {
                #pragma unroll
                for (int r = 0; r < 4; r++)
                    __stcg(&g_k[s4][(bB + b0l + r) * 128 + h], pj[r]);
            }
        }

        grid_barrier((unsigned long long)(2 * s + 2) * GRID);
    }

    // ================= epilogue: fold last step, readout =================
    if (half == 0) {
        float z0 = sm.z0s[bb][j];
        float k1 = __ldcg(&g_k[0][bme * 128 + j]);
        float k2 = __ldcg(&g_k[1][bme * 128 + j]);
        float k3 = __ldcg(&g_k[2][bme * 128 + j]);
        float k4 = __ldcg(&g_k[3][bme * 128 + j]);
        sm.ys[bb][j] = z0 + (k1 + 3.0f * (k2 + k3) + k4) * 0.125f;
    }
    __syncthreads();
    if (half == 0 && j < OUTN) {
        float acc = br[j] + x_last[bme * OUTN + j];
        #pragma unroll 8
        for (int hh = 0; hh < 128; hh++)
            acc = fmaf(sm.ys[bb][hh], Wr[hh * OUTN + j], acc);
        out[bme * OUTN + j] = acc;
    }
}

extern "C" void kernel_launch(void* const* d_in, const int* in_sizes, int n_in,
                              void* d_out, int out_size) {
    const float* coeffs = (const float*)d_in[0];
    const float* x_last = (const float*)d_in[1];
    const float* Wi     = (const float*)d_in[2];
    const float* bi     = (const float*)d_in[3];
    const float* W1     = (const float*)d_in[4];
    const float* b1     = (const float*)d_in[5];
    const float* W2     = (const float*)d_in[6];
    const float* b2     = (const float*)d_in[7];
    const float* W3     = (const float*)d_in[8];
    const float* b3     = (const float*)d_in[9];
    const float* Wr     = (const float*)d_in[10];
    const float* br     = (const float*)d_in[11];
    float* out = (float*)d_out;

    static const size_t SMEM = sizeof(SmemLayout);
    cudaFuncSetAttribute(cde_kernel, cudaFuncAttributeMaxDynamicSharedMemorySize, (int)SMEM);

    void* baraddr = nullptr;
    cudaGetSymbolAddress(&baraddr, g_bar);
    cudaMemsetAsync(baraddr, 0, sizeof(unsigned long long));

    cde_kernel<<<GRID, NTHR, SMEM>>>(coeffs, x_last, Wi, bi, W1, b1, W2, b2,
                                     W3, b3, Wr, br, out);
}

// round 4
// speedup vs baseline: 1.3956x; 1.0005x over previous
#include <cuda_runtime.h>
#include <math.h>

// Problem constants
#define BN     256
#define HN     128
#define CN     32
#define OUTN   32
#define NSTAGE 256   // 64 steps * 4 RK stages
#define GRID   128
#define NTHR   512

// ---------------- device global scratch (allocation-free) ----------------
__device__ float g_k[4][BN * HN];      // k1..k4 of current step
__device__ float g_Bv[BN * HN];        // h2 for current stage
__device__ float g_dX[BN * CN];        // dX/dt at current stage time
__device__ unsigned long long g_bar;   // grid barrier counter

struct SmemLayout {
    float W3s[128][256];     // 128 KB : this CTA's 8-h slice of W3 [i][wl*32+c]
    float W1s[128][128];     // 64 KB
    float BvT[128][36];      // transposed h2 tile [i][b], padded for LDS128
    float dXs[32][36];
    float ys[2][128];
    float As[2][128];
    float P[2][2][128];      // phase-1 partial sums [half][bb][j]
    float z0s[2][128];
    float b1s[128];
    float b2s[128];
};

__device__ __forceinline__ float softplus_f(float x) {
    return fmaxf(x, 0.0f) + log1pf(__expf(-fabsf(x)));
}
__device__ __forceinline__ float tanh_fast(float x) {
    float e = __expf(2.0f * x);
    return 1.0f - __fdividef(2.0f, e + 1.0f);
}
__device__ __forceinline__ unsigned long long pk2(float lo, float hi) {
    unsigned long long r;
    asm("mov.b64 %0, {%1,%2};" : "=l"(r) : "f"(lo), "f"(hi));
    return r;
}
__device__ __forceinline__ void unpk2(unsigned long long v, float& lo, float& hi) {
    asm("mov.b64 {%0,%1}, %2;" : "=f"(lo), "=f"(hi) : "l"(v));
}
__device__ __forceinline__ void ffma2(unsigned long long& d, unsigned long long a,
                                      unsigned long long b) {
    asm("fma.rn.f32x2 %0, %1, %2, %0;" : "+l"(d) : "l"(a), "l"(b));
}

__device__ __forceinline__ void grid_barrier(unsigned long long tgt) {
    __syncthreads();
    if (threadIdx.x == 0) {
        __threadfence();
        atomicAdd(&g_bar, 1ULL);
        while (*(volatile unsigned long long*)&g_bar < tgt) { }
    }
    __syncthreads();
}

__global__ __launch_bounds__(NTHR, 1) void cde_kernel(
    const float* __restrict__ coeffs, const float* __restrict__ x_last,
    const float* __restrict__ Wi,     const float* __restrict__ bi,
    const float* __restrict__ W1,     const float* __restrict__ b1,
    const float* __restrict__ W2,     const float* __restrict__ b2,
    const float* __restrict__ W3,     const float* __restrict__ b3,
    const float* __restrict__ Wr,     const float* __restrict__ br,
    float* __restrict__ out)
{
    extern __shared__ char smraw[];
    SmemLayout& sm = *reinterpret_cast<SmemLayout*>(smraw);

    const int tid = threadIdx.x;
    const int ci  = blockIdx.x;
    const int hg  = ci & 15;          // h-group: h in [hg*8, hg*8+8)
    const int bB  = (ci >> 4) * 32;   // phase-2 b-tile base

    // ---- one-time smem loads ----
    for (int t = tid; t < 128 * 256; t += NTHR) {
        int i = t >> 8, cc = t & 255;
        sm.W3s[i][cc] = W3[i * 4096 + hg * 256 + cc];
    }
    for (int t = tid; t < 128 * 128; t += NTHR)
        sm.W1s[t >> 7][t & 127] = W1[t];
    if (tid < 128) { sm.b1s[tid] = b1[tid]; sm.b2s[tid] = b2[tid]; }

    // ---- phase-2 mapping ----
    const int wid  = tid >> 5;
    const int lane = tid & 31;
    const int wl   = wid & 7;         // local h
    const int sub  = wid >> 3;        // b-half (0/1)
    const int cg   = lane & 7;        // c-group of 4
    const int bgr  = lane >> 3;       // b-group of 4
    const int c0   = cg * 4;
    const int b0l  = sub * 16 + bgr * 4;   // 4 b-rows per thread
    const int h    = hg * 8 + wl;

    float b3v[4];
    #pragma unroll
    for (int u = 0; u < 4; u++) b3v[u] = b3[h * 32 + c0 + u];

    // ---- phase-1 mapping ----
    const int half = tid >> 8;        // i-half (0/1)
    const int rem  = tid & 255;
    const int bb   = rem >> 7;        // batch row within CTA (0/1)
    const int j    = rem & 127;
    const int bme  = ci * 2 + bb;

    __syncthreads();

    for (int s = 0; s < NSTAGE; s++) {
        const int s4 = s & 3;
        const int n  = s >> 2;

        // ============ phase 1 : y, dX, h1, h2  (2 batch rows / CTA) ============
        if (half == 0) {
            float y;
            if (s == 0) {
                float acc = bi[j];
                const float* cb = coeffs + bme * 8192;
                #pragma unroll
                for (int c = 0; c < CN; c++) acc = fmaf(cb[c], Wi[c * 128 + j], acc);
                sm.z0s[bb][j] = acc;
                y = acc;
            } else {
                float z0 = sm.z0s[bb][j];
                if (s4 == 0) {
                    float k1 = __ldcg(&g_k[0][bme * 128 + j]);
                    float k2 = __ldcg(&g_k[1][bme * 128 + j]);
                    float k3 = __ldcg(&g_k[2][bme * 128 + j]);
                    float k4 = __ldcg(&g_k[3][bme * 128 + j]);
                    z0 += (k1 + 3.0f * (k2 + k3) + k4) * 0.125f;
                    sm.z0s[bb][j] = z0;
                    y = z0;
                } else if (s4 == 1) {
                    y = z0 + __ldcg(&g_k[0][bme * 128 + j]) * (1.0f / 3.0f);
                } else if (s4 == 2) {
                    y = z0 + __ldcg(&g_k[1][bme * 128 + j])
                           - __ldcg(&g_k[0][bme * 128 + j]) * (1.0f / 3.0f);
                } else {
                    y = z0 + __ldcg(&g_k[0][bme * 128 + j])
                           - __ldcg(&g_k[1][bme * 128 + j])
                           + __ldcg(&g_k[2][bme * 128 + j]);
                }
            }
            sm.ys[bb][j] = y;

            if (j < CN) {
                float t;
                if      (s4 == 0) t = (float)n;
                else if (s4 == 1) t = (float)n + (1.0f / 3.0f);
                else if (s4 == 2) t = (float)n + (2.0f / 3.0f);
                else              t = (float)(n + 1);
                int   pid  = (int)floorf(t); if (pid > 63) pid = 63;
                float frac = t - (float)pid;
                const float* cb = coeffs + bme * 8192 + pid * 128;
                float dv = fmaf(fmaf(cb[96 + j], frac, cb[64 + j]), frac, cb[32 + j]);
                __stcg(&g_dX[bme * 32 + j], dv);
            }
        }
        __syncthreads();

        {   // matvec1 (i-split over halves)
            const int i0 = half * 64;
            float acc = 0.0f;
            #pragma unroll 8
            for (int i = 0; i < 64; i++)
                acc = fmaf(sm.ys[bb][i0 + i], sm.W1s[i0 + i][j], acc);
            sm.P[half][bb][j] = acc;
        }
        __syncthreads();
        if (half == 0)
            sm.As[bb][j] = softplus_f(sm.P[0][bb][j] + sm.P[1][bb][j] + sm.b1s[j]);
        __syncthreads();
        {   // matvec2
            const int i0 = half * 64;
            float acc = 0.0f;
            #pragma unroll 8
            for (int i = 0; i < 64; i++)
                acc = fmaf(sm.As[bb][i0 + i], __ldg(&W2[(i0 + i) * 128 + j]), acc);
            sm.P[half][bb][j] = acc;
        }
        __syncthreads();
        if (half == 0)
            __stcg(&g_Bv[bme * 128 + j],
                   softplus_f(sm.P[0][bb][j] + sm.P[1][bb][j] + sm.b2s[j]));

        grid_barrier((unsigned long long)(2 * s + 1) * GRID);

        // ============ phase 2 : k = tanh(h2 @ W3 + b3) . dX  (32b x 8h) ============
        {
            for (int t = tid; t < 32 * 128; t += NTHR) {
                int r = t >> 7, q = t & 127;
                sm.BvT[q][r] = __ldcg(&g_Bv[(bB + r) * 128 + q]);
            }
            for (int t = tid; t < 32 * 32; t += NTHR) {
                int r = t >> 5, q = t & 31;
                sm.dXs[r][q] = __ldcg(&g_dX[(bB + r) * 32 + q]);
            }
            __syncthreads();

            unsigned long long acc[2][4];
            #pragma unroll
            for (int p = 0; p < 2; p++)
                #pragma unroll
                for (int u = 0; u < 4; u++) acc[p][u] = 0ULL;

            #pragma unroll 4
            for (int i = 0; i < 128; i++) {
                float4 w4 = *reinterpret_cast<const float4*>(&sm.W3s[i][wl * 32 + c0]);
                ulonglong2 bv = *reinterpret_cast<const ulonglong2*>(&sm.BvT[i][b0l]);
                unsigned long long w0 = pk2(w4.x, w4.x);
                unsigned long long w1d = pk2(w4.y, w4.y);
                unsigned long long w2d = pk2(w4.z, w4.z);
                unsigned long long w3d = pk2(w4.w, w4.w);
                ffma2(acc[0][0], bv.x, w0);
                ffma2(acc[0][1], bv.x, w1d);
                ffma2(acc[0][2], bv.x, w2d);
                ffma2(acc[0][3], bv.x, w3d);
                ffma2(acc[1][0], bv.y, w0);
                ffma2(acc[1][1], bv.y, w1d);
                ffma2(acc[1][2], bv.y, w2d);
                ffma2(acc[1][3], bv.y, w3d);
            }

            float pj[4] = {0.0f, 0.0f, 0.0f, 0.0f};
            #pragma unroll
            for (int p = 0; p < 2; p++) {
                #pragma unroll
                for (int u = 0; u < 4; u++) {
                    float lo, hi;
                    unpk2(acc[p][u], lo, hi);
                    pj[2 * p]     = fmaf(tanh_fast(lo + b3v[u]),
                                         sm.dXs[b0l + 2 * p][c0 + u], pj[2 * p]);
                    pj[2 * p + 1] = fmaf(tanh_fast(hi + b3v[u]),
                                         sm.dXs[b0l + 2 * p + 1][c0 + u], pj[2 * p + 1]);
                }
            }
            #pragma unroll
            for (int m = 1; m < 8; m <<= 1)
                #pragma unroll
                for (int r = 0; r < 4; r++)
                    pj[r] += __shfl_xor_sync(0xffffffffu, pj[r], m);

            if (cg == 0) {
                #pragma unroll
                for (int r = 0; r < 4; r++)
                    __stcg(&g_k[s4][(bB + b0l + r) * 128 + h], pj[r]);
            }
        }

        grid_barrier((unsigned long long)(2 * s + 2) * GRID);
    }

    // ================= epilogue: fold last step, readout =================
    if (half == 0) {
        float z0 = sm.z0s[bb][j];
        float k1 = __ldcg(&g_k[0][bme * 128 + j]);
        float k2 = __ldcg(&g_k[1][bme * 128 + j]);
        float k3 = __ldcg(&g_k[2][bme * 128 + j]);
        float k4 = __ldcg(&g_k[3][bme * 128 + j]);
        sm.ys[bb][j] = z0 + (k1 + 3.0f * (k2 + k3) + k4) * 0.125f;
    }
    __syncthreads();
    if (half == 0 && j < OUTN) {
        float acc = br[j] + x_last[bme * OUTN + j];
        #pragma unroll 8
        for (int hh = 0; hh < 128; hh++)
            acc = fmaf(sm.ys[bb][hh], Wr[hh * OUTN + j], acc);
        out[bme * OUTN + j] = acc;
    }
}

extern "C" void kernel_launch(void* const* d_in, const int* in_sizes, int n_in,
                              void* d_out, int out_size) {
    const float* coeffs = (const float*)d_in[0];
    const float* x_last = (const float*)d_in[1];
    const float* Wi     = (const float*)d_in[2];
    const float* bi     = (const float*)d_in[3];
    const float* W1     = (const float*)d_in[4];
    const float* b1     = (const float*)d_in[5];
    const float* W2     = (const float*)d_in[6];
    const float* b2     = (const float*)d_in[7];
    const float* W3     = (const float*)d_in[8];
    const float* b3     = (const float*)d_in[9];
    const float* Wr     = (const float*)d_in[10];
    const float* br     = (const float*)d_in[11];
    float* out = (float*)d_out;

    static const size_t SMEM = sizeof(SmemLayout);
    cudaFuncSetAttribute(cde_kernel, cudaFuncAttributeMaxDynamicSharedMemorySize, (int)SMEM);

    void* baraddr = nullptr;
    cudaGetSymbolAddress(&baraddr, g_bar);
    cudaMemsetAsync(baraddr, 0, sizeof(unsigned long long));

    cde_kernel<<<GRID, NTHR, SMEM>>>(coeffs, x_last, Wi, bi, W1, b1, W2, b2,
                                     W3, b3, Wr, br, out);
}

// round 5
// speedup vs baseline: 1.3967x; 1.0008x over previous
#include <cuda_runtime.h>
#include <math.h>

// Problem constants
#define BN     256
#define HN     128
#define CN     32
#define OUTN   32
#define NSTAGE 256   // 64 steps * 4 RK stages
#define GRID   128
#define NTHR   512

// ---------------- device global scratch (allocation-free) ----------------
__device__ float g_k[4][BN * HN];      // k1..k4 of current step
__device__ float g_Bv[BN * HN];        // h2 for current stage
__device__ float g_dX[BN * CN];        // dX/dt at current stage time
__device__ unsigned long long g_bar;   // grid barrier counter

struct SmemLayout {
    float W3s[128][256];     // 128 KB : this CTA's 8-h slice of W3 [i][wl*32+c]
    float W1s[128][128];     // 64 KB
    float BvT[128][36];      // transposed h2 tile [i][b], padded for LDS128
    float dXs[32][36];
    float ys[2][128];
    float As[2][128];
    float P[2][2][128];      // phase-1 partial sums [half][bb][j]
    float z0s[2][128];
    float b1s[128];
    float b2s[128];
};

__device__ __forceinline__ float softplus_f(float x) {
    return fmaxf(x, 0.0f) + log1pf(__expf(-fabsf(x)));
}
__device__ __forceinline__ float tanh_fast(float x) {
    float e = __expf(2.0f * x);
    return 1.0f - __fdividef(2.0f, e + 1.0f);
}
__device__ __forceinline__ unsigned long long pk2(float lo, float hi) {
    unsigned long long r;
    asm("mov.b64 %0, {%1,%2};" : "=l"(r) : "f"(lo), "f"(hi));
    return r;
}
__device__ __forceinline__ void unpk2(unsigned long long v, float& lo, float& hi) {
    asm("mov.b64 {%0,%1}, %2;" : "=f"(lo), "=f"(hi) : "l"(v));
}
__device__ __forceinline__ void ffma2(unsigned long long& d, unsigned long long a,
                                      unsigned long long b) {
    asm("fma.rn.f32x2 %0, %1, %2, %0;" : "+l"(d) : "l"(a), "l"(b));
}

__device__ __forceinline__ void grid_barrier(unsigned long long tgt) {
    __syncthreads();
    if (threadIdx.x == 0) {
        __threadfence();
        atomicAdd(&g_bar, 1ULL);
        while (*(volatile unsigned long long*)&g_bar < tgt) { }
    }
    __syncthreads();
}

__global__ __launch_bounds__(NTHR, 1) void cde_kernel(
    const float* __restrict__ coeffs, const float* __restrict__ x_last,
    const float* __restrict__ Wi,     const float* __restrict__ bi,
    const float* __restrict__ W1,     const float* __restrict__ b1,
    const float* __restrict__ W2,     const float* __restrict__ b2,
    const float* __restrict__ W3,     const float* __restrict__ b3,
    const float* __restrict__ Wr,     const float* __restrict__ br,
    float* __restrict__ out)
{
    extern __shared__ char smraw[];
    SmemLayout& sm = *reinterpret_cast<SmemLayout*>(smraw);

    const int tid = threadIdx.x;
    const int ci  = blockIdx.x;
    const int hg  = ci & 15;          // h-group: h in [hg*8, hg*8+8)
    const int bB  = (ci >> 4) * 32;   // phase-2 b-tile base

    // ---- one-time smem loads ----
    for (int t = tid; t < 128 * 256; t += NTHR) {
        int i = t >> 8, cc = t & 255;
        sm.W3s[i][cc] = W3[i * 4096 + hg * 256 + cc];
    }
    for (int t = tid; t < 128 * 128; t += NTHR)
        sm.W1s[t >> 7][t & 127] = W1[t];
    if (tid < 128) { sm.b1s[tid] = b1[tid]; sm.b2s[tid] = b2[tid]; }

    // ---- phase-2 mapping ----
    const int wid  = tid >> 5;
    const int lane = tid & 31;
    const int wl   = wid & 7;         // local h
    const int sub  = wid >> 3;        // b-half (0/1)
    const int cg   = lane & 7;        // c-group of 4
    const int bgr  = lane >> 3;       // b-group of 4
    const int c0   = cg * 4;
    const int b0l  = sub * 16 + bgr * 4;   // 4 b-rows per thread
    const int h    = hg * 8 + wl;

    float b3v[4];
    #pragma unroll
    for (int u = 0; u < 4; u++) b3v[u] = b3[h * 32 + c0 + u];

    // ---- phase-1 mapping ----
    const int half = tid >> 8;        // i-half (0/1)
    const int rem  = tid & 255;
    const int bb   = rem >> 7;        // batch row within CTA (0/1)
    const int j    = rem & 127;
    const int bme  = ci * 2 + bb;

    __syncthreads();

    for (int s = 0; s < NSTAGE; s++) {
        const int s4 = s & 3;
        const int n  = s >> 2;

        // ============ phase 1 : y, dX, h1, h2  (2 batch rows / CTA) ============
        if (half == 0) {
            float y;
            if (s == 0) {
                float acc = bi[j];
                const float* cb = coeffs + bme * 8192;
                #pragma unroll
                for (int c = 0; c < CN; c++) acc = fmaf(cb[c], Wi[c * 128 + j], acc);
                sm.z0s[bb][j] = acc;
                y = acc;
            } else {
                float z0 = sm.z0s[bb][j];
                if (s4 == 0) {
                    float k1 = __ldcg(&g_k[0][bme * 128 + j]);
                    float k2 = __ldcg(&g_k[1][bme * 128 + j]);
                    float k3 = __ldcg(&g_k[2][bme * 128 + j]);
                    float k4 = __ldcg(&g_k[3][bme * 128 + j]);
                    z0 += (k1 + 3.0f * (k2 + k3) + k4) * 0.125f;
                    sm.z0s[bb][j] = z0;
                    y = z0;
                } else if (s4 == 1) {
                    y = z0 + __ldcg(&g_k[0][bme * 128 + j]) * (1.0f / 3.0f);
                } else if (s4 == 2) {
                    y = z0 + __ldcg(&g_k[1][bme * 128 + j])
                           - __ldcg(&g_k[0][bme * 128 + j]) * (1.0f / 3.0f);
                } else {
                    y = z0 + __ldcg(&g_k[0][bme * 128 + j])
                           - __ldcg(&g_k[1][bme * 128 + j])
                           + __ldcg(&g_k[2][bme * 128 + j]);
                }
            }
            sm.ys[bb][j] = y;

            if (j < CN) {
                float t;
                if      (s4 == 0) t = (float)n;
                else if (s4 == 1) t = (float)n + (1.0f / 3.0f);
                else if (s4 == 2) t = (float)n + (2.0f / 3.0f);
                else              t = (float)(n + 1);
                int   pid  = (int)floorf(t); if (pid > 63) pid = 63;
                float frac = t - (float)pid;
                const float* cb = coeffs + bme * 8192 + pid * 128;
                float dv = fmaf(fmaf(cb[96 + j], frac, cb[64 + j]), frac, cb[32 + j]);
                __stcg(&g_dX[bme * 32 + j], dv);
            }
        }
        __syncthreads();

        {   // matvec1 (i-split over halves)
            const int i0 = half * 64;
            float acc = 0.0f;
            #pragma unroll 8
            for (int i = 0; i < 64; i++)
                acc = fmaf(sm.ys[bb][i0 + i], sm.W1s[i0 + i][j], acc);
            sm.P[half][bb][j] = acc;
        }
        __syncthreads();
        if (half == 0)
            sm.As[bb][j] = softplus_f(sm.P[0][bb][j] + sm.P[1][bb][j] + sm.b1s[j]);
        __syncthreads();
        {   // matvec2
            const int i0 = half * 64;
            float acc = 0.0f;
            #pragma unroll 8
            for (int i = 0; i < 64; i++)
                acc = fmaf(sm.As[bb][i0 + i], __ldg(&W2[(i0 + i) * 128 + j]), acc);
            sm.P[half][bb][j] = acc;
        }
        __syncthreads();
        if (half == 0)
            __stcg(&g_Bv[bme * 128 + j],
                   softplus_f(sm.P[0][bb][j] + sm.P[1][bb][j] + sm.b2s[j]));

        grid_barrier((unsigned long long)(2 * s + 1) * GRID);

        // ============ phase 2 : k = tanh(h2 @ W3 + b3) . dX  (32b x 8h) ============
        {
            for (int t = tid; t < 32 * 128; t += NTHR) {
                int r = t >> 7, q = t & 127;
                sm.BvT[q][r] = __ldcg(&g_Bv[(bB + r) * 128 + q]);
            }
            for (int t = tid; t < 32 * 32; t += NTHR) {
                int r = t >> 5, q = t & 31;
                sm.dXs[r][q] = __ldcg(&g_dX[(bB + r) * 32 + q]);
            }
            __syncthreads();

            unsigned long long acc[2][4];
            #pragma unroll
            for (int p = 0; p < 2; p++)
                #pragma unroll
                for (int u = 0; u < 4; u++) acc[p][u] = 0ULL;

            #pragma unroll 4
            for (int i = 0; i < 128; i++) {
                float4 w4 = *reinterpret_cast<const float4*>(&sm.W3s[i][wl * 32 + c0]);
                ulonglong2 bv = *reinterpret_cast<const ulonglong2*>(&sm.BvT[i][b0l]);
                unsigned long long w0 = pk2(w4.x, w4.x);
                unsigned long long w1d = pk2(w4.y, w4.y);
                unsigned long long w2d = pk2(w4.z, w4.z);
                unsigned long long w3d = pk2(w4.w, w4.w);
                ffma2(acc[0][0], bv.x, w0);
                ffma2(acc[0][1], bv.x, w1d);
                ffma2(acc[0][2], bv.x, w2d);
                ffma2(acc[0][3], bv.x, w3d);
                ffma2(acc[1][0], bv.y, w0);
                ffma2(acc[1][1], bv.y, w1d);
                ffma2(acc[1][2], bv.y, w2d);
                ffma2(acc[1][3], bv.y, w3d);
            }

            float pj[4] = {0.0f, 0.0f, 0.0f, 0.0f};
            #pragma unroll
            for (int p = 0; p < 2; p++) {
                #pragma unroll
                for (int u = 0; u < 4; u++) {
                    float lo, hi;
                    unpk2(acc[p][u], lo, hi);
                    pj[2 * p]     = fmaf(tanh_fast(lo + b3v[u]),
                                         sm.dXs[b0l + 2 * p][c0 + u], pj[2 * p]);
                    pj[2 * p + 1] = fmaf(tanh_fast(hi + b3v[u]),
                                         sm.dXs[b0l + 2 * p + 1][c0 + u], pj[2 * p + 1]);
                }
            }
            #pragma unroll
            for (int m = 1; m < 8; m <<= 1)
                #pragma unroll
                for (int r = 0; r < 4; r++)
                    pj[r] += __shfl_xor_sync(0xffffffffu, pj[r], m);

            if (cg == 0) {
                #pragma unroll
                for (int r = 0; r < 4; r++)
                    __stcg(&g_k[s4][(bB + b0l + r) * 128 + h], pj[r]);
            }
        }

        grid_barrier((unsigned long long)(2 * s + 2) * GRID);
    }

    // ================= epilogue: fold last step, readout =================
    if (half == 0) {
        float z0 = sm.z0s[bb][j];
        float k1 = __ldcg(&g_k[0][bme * 128 + j]);
        float k2 = __ldcg(&g_k[1][bme * 128 + j]);
        float k3 = __ldcg(&g_k[2][bme * 128 + j]);
        float k4 = __ldcg(&g_k[3][bme * 128 + j]);
        sm.ys[bb][j] = z0 + (k1 + 3.0f * (k2 + k3) + k4) * 0.125f;
    }
    __syncthreads();
    if (half == 0 && j < OUTN) {
        float acc = br[j] + x_last[bme * OUTN + j];
        #pragma unroll 8
        for (int hh = 0; hh < 128; hh++)
            acc = fmaf(sm.ys[bb][hh], Wr[hh * OUTN + j], acc);
        out[bme * OUTN + j] = acc;
    }
}

extern "C" void kernel_launch(void* const* d_in, const int* in_sizes, int n_in,
                              void* d_out, int out_size) {
    const float* coeffs = (const float*)d_in[0];
    const float* x_last = (const float*)d_in[1];
    const float* Wi     = (const float*)d_in[2];
    const float* bi     = (const float*)d_in[3];
    const float* W1     = (const float*)d_in[4];
    const float* b1     = (const float*)d_in[5];
    const float* W2     = (const float*)d_in[6];
    const float* b2     = (const float*)d_in[7];
    const float* W3     = (const float*)d_in[8];
    const float* b3     = (const float*)d_in[9];
    const float* Wr     = (const float*)d_in[10];
    const float* br     = (const float*)d_in[11];
    float* out = (float*)d_out;

    static const size_t SMEM = sizeof(SmemLayout);
    cudaFuncSetAttribute(cde_kernel, cudaFuncAttributeMaxDynamicSharedMemorySize, (int)SMEM);

    void* baraddr = nullptr;
    cudaGetSymbolAddress(&baraddr, g_bar);
    cudaMemsetAsync(baraddr, 0, sizeof(unsigned long long));

    cde_kernel<<<GRID, NTHR, SMEM>>>(coeffs, x_last, Wi, bi, W1, b1, W2, b2,
                                     W3, b3, Wr, br, out);
}